// round 8
// baseline (speedup 1.0000x reference)
#include <cuda_runtime.h>
#include <cstdint>

// Problem constants
#define Bx    8
#define Cx    256
#define Kx    19
#define HW4   4096          // HW / 4 (float4 units), HW = 128*128
#define RC    4             // c-rows per c-warp
#define CG    16            // c-rows per block (4 c-warps x RC)
#define NCG   (Cx/CG)       // 16
#define CH    32            // float4 columns per smem chunk
#define NCHT  (HW4/CH)      // 128 chunks total
#define Sx    7             // hw splits -> grid 896 ~ 3.03 waves @ 2 blk/SM
#define NBUF  4             // cp.async ring depth (prefetch distance 3)

// Scratch: att quarter-partials [s][b][c][k][quarter(4)]
__device__ float g_att_part[Sx * Bx * Cx * Kx * 4];

// ---- cp.async helpers ------------------------------------------------------
__device__ __forceinline__ void cp_async16(uint32_t saddr, const void* gptr) {
    asm volatile("cp.async.cg.shared.global [%0], [%1], 16;\n" :: "r"(saddr), "l"(gptr));
}
__device__ __forceinline__ void cp_commit() {
    asm volatile("cp.async.commit_group;\n");
}
template <int N>
__device__ __forceinline__ void cp_wait() {
    asm volatile("cp.async.wait_group %0;\n" :: "n"(N));
}
__device__ __forceinline__ uint32_t smem_u32(const void* p) {
    return (uint32_t)__cvta_generic_to_shared(p);
}
// Packed dual-FMA: acc(f32x2) += a(f32x2) * b(f32x2)   [Blackwell FFMA2]
__device__ __forceinline__ void ffma2(unsigned long long& acc,
                                      unsigned long long a, unsigned long long b) {
    asm("fma.rn.f32x2 %0, %1, %2, %0;" : "+l"(acc) : "l"(a), "l"(b));
}

// ---------------------------------------------------------------------------
// Kernel 1: att partials, k-split occupancy version.
// 8 warps/block: warps 0-3 accumulate k=0..9, warps 4-7 k=10..18, over the
// same 16 c-rows. Per-warp acc <= 40 f32x2 = 80 regs -> 2 blocks x 256 thr/SM
// = 4 warps/SMSP (double the previous occupancy; that starvation, not the
// pipeline, was the measured k_att plateau).
// Map chunks staged through 4-deep cp.async ring (one barrier per chunk).
// ---------------------------------------------------------------------------
__global__ __launch_bounds__(256, 2)
void k_att(const float* __restrict__ feat, const float* __restrict__ map) {
    __shared__ float4 smap[NBUF][Kx * CH];         // 4 x 9728 B = 38.9 KB

    const int bid  = blockIdx.x;
    const int s    = bid % Sx;
    const int cg   = (bid / Sx) % NCG;
    const int b    = bid / (Sx * NCG);
    const int tid  = threadIdx.x;
    const int w    = tid >> 5;
    const int lane = tid & 31;
    const int wc   = w & 3;                        // c-subgroup 0..3
    const int kg   = w >> 2;                       // k-group 0/1
    const int c0   = cg * CG + wc * RC;
    const int KOFF = kg * 10;                      // k base: 0 or 10
    const int KN   = kg ? 9 : 10;                  // k count: 10 or 9

    const int ch_beg = (s * NCHT) / Sx;            // 18/19-chunk ranges
    const int ch_end = ((s + 1) * NCHT) / Sx;

    const float4* __restrict__ f4 = (const float4*)feat;
    const float4* __restrict__ m4 = (const float4*)map;
    const float4* fbase = f4 + (size_t)(b * Cx + c0) * HW4;
    const float4* mbase = m4 + (size_t)(b * Kx) * HW4;

    unsigned long long acc2[10 * RC];
    #pragma unroll
    for (int i = 0; i < 10 * RC; i++) acc2[i] = 0ull;

    // map-chunk loader: 19*32 = 608 float4 by 256 threads (smem writes only)
    auto load_map_chunk = [&](int chunk) {
        const float4* src = mbase + chunk * CH;
        uint32_t sb = smem_u32(&smap[chunk & (NBUF - 1)][0]);
        #pragma unroll
        for (int j = 0; j < 2; j++) {
            int e = tid + j * 256;                 // e = k*CH + col
            cp_async16(sb + e * 16, src + (size_t)(e >> 5) * HW4 + (e & 31));
        }
        if (tid < Kx * CH - 512) {                 // last 96
            int e = tid + 512;
            cp_async16(sb + e * 16, src + (size_t)(e >> 5) * HW4 + (e & 31));
        }
    };

    // Prologue: 3 groups in flight (chunks ch_beg .. ch_beg+2).
    #pragma unroll
    for (int p = 0; p < NBUF - 1; p++) {
        if (ch_beg + p < ch_end) load_map_chunk(ch_beg + p);
        cp_commit();
    }

    #pragma unroll 1
    for (int ch = ch_beg; ch < ch_end; ch++) {
        cp_wait<NBUF - 2>();                       // chunk ch resident
        __syncthreads();                           // all warps done with ch-1

        if (ch + NBUF - 1 < ch_end) load_map_chunk(ch + NBUF - 1);
        cp_commit();                               // commit even if empty

        // Feature for this chunk (L1-hit for the second k-group; 4 warps/SMSP
        // cover the latency).
        const int col = ch * CH + lane;
        ulonglong2 fcv[RC];
        #pragma unroll
        for (int c = 0; c < RC; c++)
            fcv[c] = *(const ulonglong2*)(fbase + (size_t)c * HW4 + col);

        const float4* sb = smap[ch & (NBUF - 1)];
        #pragma unroll
        for (int j = 0; j < 10; j++) {
            if (j < KN) {
                ulonglong2 mv = *(const ulonglong2*)(&sb[(KOFF + j) * CH + lane]);
                #pragma unroll
                for (int c = 0; c < RC; c++)
                    ffma2(acc2[j * RC + c], fcv[c].x, mv.x);
                #pragma unroll
                for (int c = 0; c < RC; c++)
                    ffma2(acc2[j * RC + c], fcv[c].y, mv.y);
            }
        }
    }

    // Collapse packed pairs; 3-round lane reduction -> quarter partials.
    #pragma unroll
    for (int j = 0; j < 10; j++) {
        if (j < KN) {
            #pragma unroll
            for (int c = 0; c < RC; c++) {
                unsigned long long a = acc2[j * RC + c];
                float v = __uint_as_float((uint32_t)a)
                        + __uint_as_float((uint32_t)(a >> 32));
                v += __shfl_down_sync(0xffffffffu, v, 16);
                v += __shfl_down_sync(0xffffffffu, v, 8);
                v += __shfl_down_sync(0xffffffffu, v, 4);
                acc2[j * RC + c] = (unsigned long long)__float_as_uint(v);
            }
        }
    }

    if (lane < 4) {
        #pragma unroll
        for (int j = 0; j < 10; j++) {
            if (j < KN) {
                #pragma unroll
                for (int c = 0; c < RC; c++) {
                    float v = __uint_as_float((uint32_t)acc2[j * RC + c]);
                    g_att_part[((((size_t)s * Bx + b) * Cx + (c0 + c)) * Kx
                                + (KOFF + j)) * 4 + lane] = v;
                }
            }
        }
    }
}

// ---------------------------------------------------------------------------
// Kernel 2 (fused scale+apply): one block per (b,c) row. Plain loads/stores.
// ---------------------------------------------------------------------------
__global__ __launch_bounds__(256)
void k_apply(const float* __restrict__ feat, const float* __restrict__ gamma,
             float* __restrict__ out) {
    __shared__ float sh[Kx + 1];
    const int row = blockIdx.x;                    // b*Cx + c
    const int tid = threadIdx.x;

    if (tid < Kx) {
        const float* p = g_att_part + (size_t)row * Kx * 4 + tid * 4;
        float a = 0.f;
        #pragma unroll
        for (int s = 0; s < Sx; s++) {
            const float* ps = p + (size_t)s * Bx * Cx * Kx * 4;
            a += ps[0] + ps[1] + ps[2] + ps[3];
        }
        sh[tid] = gamma[tid] * (1.f / (1.f + __expf(-a)));
    }
    __syncthreads();
    if (tid == 0) {
        float sc = 0.f;
        #pragma unroll
        for (int k = 0; k < Kx; k++) sc += sh[k];
        sh[Kx] = 1.f + sc;
    }
    __syncthreads();
    const float s = sh[Kx];

    const float4* __restrict__ fr = (const float4*)feat + (size_t)row * HW4;
    float4* __restrict__ orow = (float4*)out + (size_t)row * HW4;
    #pragma unroll 4
    for (int i = tid; i < HW4; i += 256) {
        float4 f = fr[i];
        f.x *= s; f.y *= s; f.z *= s; f.w *= s;
        orow[i] = f;
    }
}

// ---------------------------------------------------------------------------
extern "C" void kernel_launch(void* const* d_in, const int* in_sizes, int n_in,
                              void* d_out, int out_size) {
    const float* feat  = (const float*)d_in[0];
    const float* map_  = (const float*)d_in[1];
    const float* gamma = (const float*)d_in[2];
    float* out = (float*)d_out;

    k_att  <<<Bx * NCG * Sx, 256>>>(feat, map_);
    k_apply<<<Bx * Cx, 256>>>(feat, gamma, out);
}